// round 14
// baseline (speedup 1.0000x reference)
#include <cuda_runtime.h>
#include <cstdint>

#define BSZ 32
#define CCH 256
#define NPX 4096
#define REGF 0.01f

#define TN  16                      // n per block
#define KB  4                       // b per chunk
#define NCHUNK (BSZ / KB)           // 8
#define BUFSZ (64 * KB * TN)        // 4096 floats (16 KB): 64 rows x 4 b x 16 n
#define NBUF 4                      // 64 KB per CTA -> 2 CTAs/SM

typedef unsigned long long ull;

// packed fp32x2 FMA (2 FMAs/instr); ptxas never emits from C++.
__device__ __forceinline__ void ffma2(ull& acc, ull a, ull b) {
    asm("fma.rn.f32x2 %0, %1, %2, %0;" : "+l"(acc) : "l"(a), "l"(b));
}
__device__ __forceinline__ unsigned smem_u32(const void* p) {
    return (unsigned)__cvta_generic_to_shared(p);
}
__device__ __forceinline__ void cp16(unsigned s, const float* g) {
    asm volatile("cp.async.cg.shared.global [%0], [%1], 16;" :: "r"(s), "l"(g));
}
#define CP_COMMIT() asm volatile("cp.async.commit_group;" ::: "memory")
#define CP_WAIT2()  asm volatile("cp.async.wait_group 2;" ::: "memory")

// ---------------------------------------------------------------------------
// Kernel 1: mean over batch. x: [B, C, N], mean: [C, N].
// ---------------------------------------------------------------------------
__global__ void mvg_mean_kernel(const float* __restrict__ x,
                                float* __restrict__ mean) {
    int idx = blockIdx.x * blockDim.x + threadIdx.x;
    const float4* x4 = (const float4*)x;
    float4 s = make_float4(0.f, 0.f, 0.f, 0.f);
    const int stride = CCH * NPX / 4;
#pragma unroll
    for (int b = 0; b < BSZ; b++) {
        float4 v = x4[b * stride + idx];
        s.x += v.x; s.y += v.y; s.z += v.z; s.w += v.w;
    }
    const float inv = 1.0f / BSZ;
    s.x *= inv; s.y *= inv; s.z *= inv; s.w *= inv;
    ((float4*)mean)[idx] = s;
}

// ---------------------------------------------------------------------------
// Kernel 2: cov[c,d,n] = (sum_b x_c x_d - B m_c m_d)/(B-1) + REG*(c==d)
// Champion per-thread geometry (8c x 8d x 2n microtile, 16 LDS.64 per
// 64 FFMA2) but block = 32c x 32d x 16n with 128 threads and 64 KB smem
// so TWO CTAs co-reside per SM (4 warps/SMSP from independent CTAs:
// one CTA's barrier/LDS bubbles are covered by the other).
// Upper-tri tile pairs (36), mirrored writes. cp.async 4 buffers,
// 3 chunks in flight, one sync per chunk. Staging fully unrolled with
// r-invariant index fields.
// ---------------------------------------------------------------------------
__global__ __launch_bounds__(128, 2)
void mvg_cov_kernel(const float* __restrict__ x,
                    const float* __restrict__ mean,
                    float* __restrict__ cov) {
    // upper-triangular tile pair (ti <= tj) from blockIdx.x in [0,36)
    int rem = blockIdx.x;
    int ti = 0, row8 = 8;
    while (rem >= row8) { rem -= row8; row8--; ti++; }
    const int tj = ti + rem;
    const bool diag = (ti == tj);
    const int n0 = blockIdx.y * TN;

    extern __shared__ float sm[];

    const int tid = threadIdx.x;
    const int tn  = tid & 7;         // n-pair index (2 n per thread)
    const int tcd = tid >> 3;
    const int tc  = tcd & 3;         // 8 c-rows
    const int td  = tcd >> 2;        // 8 d-rows

    // r-invariant staging fields: f = r*128 + tid
    const int n4 = tid & 3;          // float4 column (0..3)
    const int sb = (tid >> 2) & 3;   // batch-within-chunk
    const int r0 = tid >> 4;         // base row (0..7); row = r0 + 8r

    const float* gc_base = x + ((size_t)sb * CCH + ti * 32 + r0) * NPX + n0 + n4 * 4;
    const float* gd_base = x + ((size_t)sb * CCH + tj * 32 + r0) * NPX + n0 + n4 * 4;
    const unsigned sm_off = (unsigned)(((r0 * KB + sb) * TN + n4 * 4) * 4);

    // ---- stage chunk ck into buffer ck % NBUF (fully unrolled) ----
    auto stage = [&](int ck) {
        const unsigned dst = smem_u32(sm)
            + (unsigned)((ck & (NBUF - 1)) * BUFSZ * 4) + sm_off;
        const size_t gofs = (size_t)(ck * KB) * CCH * NPX;
        const float* gc = gc_base + gofs;
#pragma unroll
        for (int r = 0; r < 4; r++)   // c-rows r0 + 8r (0..31)
            cp16(dst + (unsigned)(r * 8 * KB * TN * 4), gc + (size_t)r * 8 * NPX);
        if (!diag) {
            const float* gd = gd_base + gofs;
            const unsigned ddst = dst + (unsigned)(32 * KB * TN * 4);
#pragma unroll
            for (int r = 0; r < 4; r++)  // d-rows
                cp16(ddst + (unsigned)(r * 8 * KB * TN * 4), gd + (size_t)r * 8 * NPX);
        }
        CP_COMMIT();
    };

    ull acc[8][8];
#pragma unroll
    for (int i = 0; i < 8; i++)
#pragma unroll
        for (int j = 0; j < 8; j++) acc[i][j] = 0ull;

    const int drow0 = diag ? 0 : 32;

    auto compute = [&](int ck) {
        const float* buf = sm + (ck & (NBUF - 1)) * BUFSZ;
        const float* pa = buf + (tc * 8) * (KB * TN) + 2 * tn;
        const float* pb = buf + (drow0 + td * 8) * (KB * TN) + 2 * tn;
#pragma unroll
        for (int bb = 0; bb < KB; bb++) {
            ull av[8], bv[8];
#pragma unroll
            for (int i = 0; i < 8; i++)
                av[i] = *(const ull*)&pa[i * (KB * TN) + bb * TN];
#pragma unroll
            for (int j = 0; j < 8; j++)
                bv[j] = *(const ull*)&pb[j * (KB * TN) + bb * TN];
#pragma unroll
            for (int i = 0; i < 8; i++)
#pragma unroll
                for (int j = 0; j < 8; j++)
                    ffma2(acc[i][j], av[i], bv[j]);
        }
    };

    // ---- pipeline: 4 buffers, 3 chunks in flight, one sync per chunk ----
    stage(0); stage(1); stage(2);
#pragma unroll
    for (int ck = 0; ck < NCHUNK; ck++) {
        CP_WAIT2();                  // groups 0..ck complete
        __syncthreads();             // data visible; prev compute done
        compute(ck);
        if (ck + 3 < NCHUNK) stage(ck + 3);
        else CP_COMMIT();            // empty group keeps wait count aligned
    }

    // ---- epilogue: mean correction, scale, reg, write + mirror ----
    const float scale = 1.0f / (BSZ - 1);
    const int n = n0 + 2 * tn;
    float2 md[8];
#pragma unroll
    for (int j = 0; j < 8; j++)
        md[j] = *(const float2*)&mean[(size_t)(tj * 32 + td * 8 + j) * NPX + n];
#pragma unroll
    for (int i = 0; i < 8; i++) {
        const int c = ti * 32 + tc * 8 + i;
        float2 mc = *(const float2*)&mean[(size_t)c * NPX + n];
#pragma unroll
        for (int j = 0; j < 8; j++) {
            const int d = tj * 32 + td * 8 + j;
            ull a = acc[i][j];
            float lo = __uint_as_float((unsigned)(a & 0xffffffffull));
            float hi = __uint_as_float((unsigned)(a >> 32));
            lo = (lo - (float)BSZ * mc.x * md[j].x) * scale;
            hi = (hi - (float)BSZ * mc.y * md[j].y) * scale;
            if (c == d) { lo += REGF; hi += REGF; }
            float2 o = make_float2(lo, hi);
            __stcs((float2*)&cov[((size_t)c * CCH + d) * NPX + n], o);
            if (!diag)
                __stcs((float2*)&cov[((size_t)d * CCH + c) * NPX + n], o);
        }
    }
}

// ---------------------------------------------------------------------------
extern "C" void kernel_launch(void* const* d_in, const int* in_sizes, int n_in,
                              void* d_out, int out_size) {
    const float* x = (const float*)d_in[0];
    float* out  = (float*)d_out;
    float* mean = out;                          // [C, N]
    float* cov  = out + (size_t)CCH * NPX;      // [C, C, N]

    mvg_mean_kernel<<<(CCH * NPX / 4) / 256, 256>>>(x, mean);

    static bool attr_set = false;
    const int smem_bytes = NBUF * BUFSZ * 4;    // 65,536 B per CTA
    if (!attr_set) {
        cudaFuncSetAttribute(mvg_cov_kernel,
                             cudaFuncAttributeMaxDynamicSharedMemorySize,
                             smem_bytes);
        attr_set = true;
    }
    dim3 grid(36, NPX / TN);                    // (36, 256)
    mvg_cov_kernel<<<grid, 128, smem_bytes>>>(x, mean, cov);
}